// round 17
// baseline (speedup 1.0000x reference)
#include <cuda_runtime.h>
#include <cuda_bf16.h>

#define NCTA 256
#define NT 320
#define TT 1024
#define BB 128
#define HH 256

__device__ float g_h[BB * HH];
__device__ float g_u[BB * HH];
__device__ unsigned g_flags[8][32][8];

__device__ __forceinline__ float4 ldcg4(const float4* p) {
    float4 v;
    asm volatile("ld.global.cg.v4.f32 {%0,%1,%2,%3}, [%4];"
                 : "=f"(v.x), "=f"(v.y), "=f"(v.z), "=f"(v.w) : "l"(p));
    return v;
}
__device__ __forceinline__ float ldcg1(const float* p) {
    float v;
    asm volatile("ld.global.cg.f32 %0, [%1];" : "=f"(v) : "l"(p));
    return v;
}
__device__ __forceinline__ unsigned ldrelax(const unsigned* p) {
    unsigned v;
    asm volatile("ld.relaxed.gpu.global.u32 %0, [%1];" : "=r"(v) : "l"(p) : "memory");
    return v;
}
__device__ __forceinline__ float fast_tanh(float x) {
    float ax = fabsf(x);
    float e = __expf(2.0f * ax);
    float r = 1.0f - 2.0f / (e + 1.0f);
    return copysignf(r, x);
}
__device__ __forceinline__ float fast_sigmoid(float x) {
    return 1.0f / (1.0f + __expf(-x));
}

// Row-group barrier: 32 CTAs (same mi), flag store + 32-lane poll in warp 0.
__device__ __forceinline__ void group_bar(unsigned* fl, int nj, unsigned base, unsigned ep) {
    __syncthreads();
    if (threadIdx.x < 32) {
        if (threadIdx.x == 0) {
            asm volatile("fence.acq_rel.gpu;" ::: "memory");
            asm volatile("st.relaxed.gpu.global.u32 [%0], %1;"
                         :: "l"(fl + nj * 8), "r"(base + ep) : "memory");
        }
        unsigned v;
        unsigned* p = fl + threadIdx.x * 8;
        do { v = ldrelax(p); }
        while (__any_sync(0xffffffffu, (v - base) < ep));
        asm volatile("fence.acq_rel.gpu;" ::: "memory");
    }
    __syncthreads();
}

// SMEM layout (floats). No staging tiles: GEMM operands are register-direct.
#define OFF_W1S 0                     // [256][44] padded
#define OFF_W2S 11264                 // [256][20] padded
#define OFF_S1  16384                 // [2][40][17]
#define OFF_S2  17744                 // [4][16][17]
#define OFF_AMP 18832                 // [16]
#define OFF_COS 18848
#define OFF_SIN 18864
#define OFF_W0  18880                 // [3][8]
#define OFF_B1  18904                 // [3][8]
#define OFF_BZ  18928                 // [8]
#define OFF_BH  18936                 // [8]
#define OFF_WOF 18944                 // [8][2] (only own columns)
#define SMEM_FLOATS 18960
#define SMEM_BYTES (SMEM_FLOATS * 4)

__global__ void __launch_bounds__(NT, 2) pgjanet_kernel(
    const float* __restrict__ x,   const float* __restrict__ h0,
    const float* __restrict__ Wa,  const float* __restrict__ ba,
    const float* __restrict__ Wp1, const float* __restrict__ bp1,
    const float* __restrict__ Wp2, const float* __restrict__ bp2,
    const float* __restrict__ Wz,  const float* __restrict__ bz,
    const float* __restrict__ Wh,  const float* __restrict__ bh,
    const float* __restrict__ Wo,  const float* __restrict__ bo,
    float* __restrict__ out)
{
    extern __shared__ float sm[];
    float* W1s = sm + OFF_W1S;
    float* W2s = sm + OFF_W2S;
    float* S1  = sm + OFF_S1;
    float* S2  = sm + OFF_S2;
    float* s_amp = sm + OFF_AMP;
    float* s_cos = sm + OFF_COS;
    float* s_sin = sm + OFF_SIN;
    float* s_w0  = sm + OFF_W0;
    float* s_b1  = sm + OFF_B1;
    float* s_bz  = sm + OFF_BZ;
    float* s_bh  = sm + OFF_BH;
    float* s_Wo  = sm + OFF_WOF;

    const int tid  = threadIdx.x;
    const int lane = tid & 31;
    const int wid  = tid >> 5;
    const int nj = blockIdx.x & 31;   // column slice (8 cols)
    const int mi = blockIdx.x >> 5;   // row group (16 rows), 8 groups
    const int j0 = nj * 8;
    const int r0 = mi * 16;

    unsigned* fl = &g_flags[mi][0][0];

    unsigned base = 0;
    if (tid < 32)
        base = ldrelax(fl + nj * 8);   // own flag; only warp 0 uses base

    // ---- init out slice to bias (rows r0..r0+15, t in [nj*32, nj*32+32)) ----
    // Ordered before any epi2 atomicAdd by the first group barrier.
    for (int idx = tid; idx < 1024; idx += NT) {
        int r = idx >> 6, rem = idx & 63;
        out[(r0 + r) * TT * 2 + nj * 64 + rem] = __ldg(bo + (rem & 1));
    }

    // ---- preload loop-invariant weights into SMEM (padded strides) ----
    for (int idx = tid; idx < 256 * 40; idx += NT) {
        int k = idx / 40, nn = idx % 40;
        int mat = nn >> 3, j = j0 + (nn & 7);
        float v;
        if      (mat == 0) v = Wa [(1 + k) * HH + j];
        else if (mat == 1) v = Wp1[(1 + k) * HH + j];
        else if (mat == 2) v = Wp2[(1 + k) * HH + j];
        else if (mat == 3) v = Wz [(HH + k) * HH + j];
        else               v = Wh [(HH + k) * HH + j];
        W1s[k * 44 + nn] = v;
    }
    for (int idx = tid; idx < 256 * 16; idx += NT) {
        int k = idx / 16, nn = idx % 16;
        int j = j0 + (nn & 7);
        W2s[k * 20 + nn] = (nn < 8) ? Wz[k * HH + j] : Wh[k * HH + j];
    }
    if (tid < 8) {
        int j = j0 + tid;
        s_w0[tid]      = Wa [j];  s_w0[8 + tid]  = Wp1[j];  s_w0[16 + tid] = Wp2[j];
        s_b1[tid]      = ba [j];  s_b1[8 + tid]  = bp1[j];  s_b1[16 + tid] = bp2[j];
        s_bz[tid] = bz[j];        s_bh[tid] = bh[j];
        s_Wo[tid * 2]     = Wo[j * 2];
        s_Wo[tid * 2 + 1] = Wo[j * 2 + 1];
    }

    unsigned ep = 0;

    for (int t = 0; t < TT; ++t) {
        const float* hsrc = (t == 0) ? h0 : g_h;

        // ---- warp 0: per-row x inputs (visible to epi1 via post-GEMM1 sync) ----
        if (tid < 16) {
            const float* xp = x + (((r0 + tid) * TT) + t) * 2;
            float amp = __ldg(xp), ph = __ldg(xp + 1);
            s_amp[tid] = amp;
            float sv, cv; sincosf(ph, &sv, &cv);
            s_sin[tid] = sv; s_cos[tid] = cv;
        }

        // ---- GEMM1: 10 warps = 5 cg (8 cols) x 2 kh; lane halves take
        //      contiguous 16-kc sub-slices; h register-direct from L2 ----
        {
            int cg = wid % 5, kh = wid / 5;
            int r = lane & 15, sub = lane >> 4;
            int q = kh * 2 + sub;                       // k sixteenth-slice id
            const float4* hp = (const float4*)(hsrc + (r0 + r) * HH) + q * 16;
            float4 hb[4];
            hb[0] = ldcg4(hp + 0); hb[1] = ldcg4(hp + 1);
            hb[2] = ldcg4(hp + 2); hb[3] = ldcg4(hp + 3);
            float a0 = 0.f, a1 = 0.f, a2 = 0.f, a3 = 0.f;
            float a4 = 0.f, a5 = 0.f, a6 = 0.f, a7 = 0.f;
            const float* wp = W1s + cg * 8;
            #pragma unroll
            for (int mm = 0; mm < 16; ++mm) {
                float4 hv = hb[mm & 3];
                if (mm < 12) hb[mm & 3] = ldcg4(hp + mm + 4);
                int m = q * 16 + mm;
                #pragma unroll
                for (int d = 0; d < 4; ++d) {
                    float hk = (d == 0) ? hv.x : (d == 1) ? hv.y : (d == 2) ? hv.z : hv.w;
                    float4 w0 = *(const float4*)&wp[(4 * m + d) * 44];
                    float4 w1 = *(const float4*)&wp[(4 * m + d) * 44 + 4];
                    a0 += hk * w0.x; a1 += hk * w0.y; a2 += hk * w0.z; a3 += hk * w0.w;
                    a4 += hk * w1.x; a5 += hk * w1.y; a6 += hk * w1.z; a7 += hk * w1.w;
                }
            }
            a0 += __shfl_down_sync(0xffffffffu, a0, 16);
            a1 += __shfl_down_sync(0xffffffffu, a1, 16);
            a2 += __shfl_down_sync(0xffffffffu, a2, 16);
            a3 += __shfl_down_sync(0xffffffffu, a3, 16);
            a4 += __shfl_down_sync(0xffffffffu, a4, 16);
            a5 += __shfl_down_sync(0xffffffffu, a5, 16);
            a6 += __shfl_down_sync(0xffffffffu, a6, 16);
            a7 += __shfl_down_sync(0xffffffffu, a7, 16);
            if (sub == 0) {
                float* s = S1 + kh * 680 + (cg * 8) * 17 + r;
                s[0]   = a0; s[17]  = a1; s[34]  = a2; s[51]  = a3;
                s[68]  = a4; s[85]  = a5; s[102] = a6; s[119] = a7;
            }
        }
        __syncthreads();

        // ---- epilogue 1: a, p1, p2 -> u (128 threads: 16 rows x 8 cols) ----
        if (tid < 128) {
            int jj = tid & 7, r = tid >> 3;
            float sa  = S1[(0  + jj) * 17 + r] + S1[680 + (0  + jj) * 17 + r];
            float sp1 = S1[(8  + jj) * 17 + r] + S1[680 + (8  + jj) * 17 + r];
            float sp2 = S1[(16 + jj) * 17 + r] + S1[680 + (16 + jj) * 17 + r];
            float a  = fast_tanh(sa  + s_amp[r] * s_w0[jj]      + s_b1[jj]);
            float p1 = fast_tanh(sp1 + s_cos[r] * s_w0[8 + jj]  + s_b1[8 + jj]);
            float p2 = fast_tanh(sp2 + s_sin[r] * s_w0[16 + jj] + s_b1[16 + jj]);
            g_u[(r0 + r) * HH + j0 + jj] =
                a * p1 * p2 * (1.f - a) * (1.f - p1) * (1.f - p2);
        }
        group_bar(fl, nj, base, ++ep);

        // ---- GEMM2: warps 0-7 = 2 cg2 (8 cols) x 4 ke; u register-direct ----
        if (wid < 8) {
            int cg2 = wid & 1, ke = wid >> 1;
            int r = lane & 15, sub = lane >> 4;
            int q = ke * 2 + sub;                      // 8-kc sub-slice
            const float4* up = (const float4*)(g_u + (r0 + r) * HH) + q * 8;
            float4 ub[4];
            ub[0] = ldcg4(up + 0); ub[1] = ldcg4(up + 1);
            ub[2] = ldcg4(up + 2); ub[3] = ldcg4(up + 3);
            float a0 = 0.f, a1 = 0.f, a2 = 0.f, a3 = 0.f;
            float a4 = 0.f, a5 = 0.f, a6 = 0.f, a7 = 0.f;
            const float* wp = W2s + cg2 * 8;
            #pragma unroll
            for (int mm = 0; mm < 8; ++mm) {
                float4 uv = ub[mm & 3];
                if (mm < 4) ub[mm & 3] = ldcg4(up + mm + 4);
                int m = q * 8 + mm;
                #pragma unroll
                for (int d = 0; d < 4; ++d) {
                    float uk = (d == 0) ? uv.x : (d == 1) ? uv.y : (d == 2) ? uv.z : uv.w;
                    float4 w0 = *(const float4*)&wp[(4 * m + d) * 20];
                    float4 w1 = *(const float4*)&wp[(4 * m + d) * 20 + 4];
                    a0 += uk * w0.x; a1 += uk * w0.y; a2 += uk * w0.z; a3 += uk * w0.w;
                    a4 += uk * w1.x; a5 += uk * w1.y; a6 += uk * w1.z; a7 += uk * w1.w;
                }
            }
            a0 += __shfl_down_sync(0xffffffffu, a0, 16);
            a1 += __shfl_down_sync(0xffffffffu, a1, 16);
            a2 += __shfl_down_sync(0xffffffffu, a2, 16);
            a3 += __shfl_down_sync(0xffffffffu, a3, 16);
            a4 += __shfl_down_sync(0xffffffffu, a4, 16);
            a5 += __shfl_down_sync(0xffffffffu, a5, 16);
            a6 += __shfl_down_sync(0xffffffffu, a6, 16);
            a7 += __shfl_down_sync(0xffffffffu, a7, 16);
            if (sub == 0) {
                float* s = S2 + ke * 272 + (cg2 * 8) * 17 + r;
                s[0]   = a0; s[17]  = a1; s[34]  = a2; s[51]  = a3;
                s[68]  = a4; s[85]  = a5; s[102] = a6; s[119] = a7;
            }
        }
        __syncthreads();

        // ---- epilogue 2: z, h_cand, h_new, fused out-projection partial ----
        if (tid < 128) {
            int jj = tid & 7, r = tid >> 3;
            int j = j0 + jj;
            float zp = s_bz[jj], hp = s_bh[jj];
            #pragma unroll
            for (int e = 0; e < 4; ++e) {
                zp += S2[e * 272 + jj * 17 + r];
                hp += S2[e * 272 + (8 + jj) * 17 + r];
            }
            zp += S1[(24 + jj) * 17 + r] + S1[680 + (24 + jj) * 17 + r];
            hp += S1[(32 + jj) * 17 + r] + S1[680 + (32 + jj) * 17 + r];
            float z  = fast_sigmoid(zp);
            float hc = fast_tanh(hp);
            float hold = ldcg1(&hsrc[(r0 + r) * HH + j]);
            float hn = z * hold + (1.f - z) * hc;
            g_h[(r0 + r) * HH + j] = hn;
            if (t == TT - 1)
                out[BB * TT * 2 + (r0 + r) * HH + j] = hn;

            // out[b,t,:] partial: reduce 8 jj lanes, one atomic per (r,o)
            float po0 = hn * s_Wo[jj * 2];
            float po1 = hn * s_Wo[jj * 2 + 1];
            po0 += __shfl_xor_sync(0xffffffffu, po0, 1);
            po0 += __shfl_xor_sync(0xffffffffu, po0, 2);
            po0 += __shfl_xor_sync(0xffffffffu, po0, 4);
            po1 += __shfl_xor_sync(0xffffffffu, po1, 1);
            po1 += __shfl_xor_sync(0xffffffffu, po1, 2);
            po1 += __shfl_xor_sync(0xffffffffu, po1, 4);
            if (jj == 0) {
                float* op = out + (((r0 + r) * TT) + t) * 2;
                atomicAdd(op,     po0);
                atomicAdd(op + 1, po1);
            }
        }
        group_bar(fl, nj, base, ++ep);
    }
}

extern "C" void kernel_launch(void* const* d_in, const int* in_sizes, int n_in,
                              void* d_out, int out_size) {
    const float* x   = (const float*)d_in[0];
    const float* h0  = (const float*)d_in[1];
    const float* Wa  = (const float*)d_in[2];
    const float* ba  = (const float*)d_in[3];
    const float* Wp1 = (const float*)d_in[4];
    const float* bp1 = (const float*)d_in[5];
    const float* Wp2 = (const float*)d_in[6];
    const float* bp2 = (const float*)d_in[7];
    const float* Wz  = (const float*)d_in[8];
    const float* bz  = (const float*)d_in[9];
    const float* Wh  = (const float*)d_in[10];
    const float* bh  = (const float*)d_in[11];
    const float* Wo  = (const float*)d_in[12];
    const float* bo  = (const float*)d_in[13];
    float* out = (float*)d_out;

    cudaFuncSetAttribute(pgjanet_kernel,
                         cudaFuncAttributeMaxDynamicSharedMemorySize, SMEM_BYTES);
    pgjanet_kernel<<<NCTA, NT, SMEM_BYTES>>>(
        x, h0, Wa, ba, Wp1, bp1, Wp2, bp2, Wz, bz, Wh, bh, Wo, bo, out);
}